// round 8
// baseline (speedup 1.0000x reference)
#include <cuda_runtime.h>
#include <cuda_bf16.h>

// Problem constants (fixed shapes from reference setup_inputs)
#define N_ 32768
#define K_ 4096
#define D_ 256

// ---------------- device scratch (no allocations allowed) ----------------
__device__ float  g_x2[N_];           // ||x_n||^2 (XLA-style warp row-reduce bits)
__device__ float  g_e2a[K_];          // ||embedding_k||^2 (pass A)
__device__ float  g_e2b[K_];          // ||new_embedding_k||^2 (pass B)
__device__ __align__(16) float g_embB[K_ * D_];   // aligned copy of new_embedding for pass B
__device__ int    g_idx1[N_];         // argmin pass A
__device__ int    g_idx2[N_];         // argmin pass B
__device__ float  g_counts[K_];       // segment counts (pass A)
__device__ float  g_dw[K_ * D_];      // segment sum of x per code
__device__ double g_loss_part[256];   // partial commitment-loss sums
__device__ float  g_nsum;             // sum(new_cs)
__device__ int    g_used[K_];         // used mask from pass B
__device__ int    g_usage_cnt;        // count(new_usage > 0)

// ---------------- helpers ----------------
__device__ __forceinline__ unsigned long long pack_min(float f, int idx) {
    unsigned u = __float_as_uint(f);
    u = (u & 0x80000000u) ? ~u : (u | 0x80000000u);   // order-preserving key
    return ((unsigned long long)u << 32) | (unsigned)idx;
}

// packed 2xfp32 FMA (each lane rounds .rn, bit-identical to scalar FFMA)
__device__ __forceinline__ unsigned long long ffma2(unsigned long long a,
                                                    unsigned long long b,
                                                    unsigned long long c) {
    unsigned long long d;
    asm("fma.rn.f32x2 %0, %1, %2, %3;" : "=l"(d) : "l"(a), "l"(b), "l"(c));
    return d;
}

// duplicate one float into both halves of a 64-bit pair
__device__ __forceinline__ unsigned long long pack2(float v) {
    unsigned long long r;
    asm("mov.b64 %0, {%1, %1};" : "=l"(r) : "f"(v));
    return r;
}

// ---------------- init: zero all scratch (graph replays!) ----------------
__global__ void init_kernel() {
    int i = blockIdx.x * blockDim.x + threadIdx.x;
    g_dw[i] = 0.0f;
    if (i < K_) { g_counts[i] = 0.0f; g_used[i] = 0; }
    if (i < 256) g_loss_part[i] = 0.0;
    if (i == 0) { g_nsum = 0.0f; g_usage_cnt = 0; }
}

// ---------------- row sum-of-squares, XLA-style warp reduce ----------------
__global__ void rowsq_kernel(const float* __restrict__ X, float* __restrict__ out, int rows) {
    int warp = (blockIdx.x * blockDim.x + threadIdx.x) >> 5;
    int lane = threadIdx.x & 31;
    if (warp >= rows) return;
    const float* row = X + (size_t)warp * D_;
    float acc = 0.0f;
    #pragma unroll
    for (int i = 0; i < 8; i++) {
        float v = row[lane + 32 * i];
        acc = __fadd_rn(acc, __fmul_rn(v, v));
    }
    #pragma unroll
    for (int o = 16; o > 0; o >>= 1)
        acc = __fadd_rn(acc, __shfl_down_sync(0xffffffffu, acc, o));
    if (lane == 0) out[warp] = acc;
}

// ---------------- fused distance-argmin SGEMM (FFMA2, X-stationary, 2 CTA/SM) ----------------
// score[n,k] = fl(fl(x2[n] - 2*dot(x_n,E_k)) + e2[k]); argmin over k, lowest-index ties.
// Block: 64 rows (stationary in smem) x 256-col tiles (B streamed in 32-d chunks).
// 256 threads; warp owns 8 consecutive rows (full-broadcast A reads); lane owns 8 cols.
// 2 CTAs/SM so barrier/memory stalls of one CTA are absorbed by the other's FFMA2s.
#define ROWS_BLK  64
#define AS_STRIDE 68
#define AS_BYTES  (256 * AS_STRIDE * 4)   // 69632
#define BS_BYTES  (32 * 256 * 4)          // 32768
#define X2S_BYTES (ROWS_BLK * 4)          // 256
#define SMEM_ARG  (AS_BYTES + BS_BYTES + X2S_BYTES)   // 102656 -> 2 CTAs/SM

__global__ void __launch_bounds__(256, 2)
argmin_kernel(const float* __restrict__ X, const float* __restrict__ E, int pass)
{
    extern __shared__ __align__(16) char smem[];
    float (*As)[AS_STRIDE] = (float (*)[AS_STRIDE])smem;          // [256 d][64 rows]
    float (*Bs)[256]       = (float (*)[256])(smem + AS_BYTES);   // [32 d][256 cols]
    float* x2s             = (float*)(smem + AS_BYTES + BS_BYTES);

    const float* __restrict__ e2 = pass ? g_e2b : g_e2a;
    int* __restrict__ out_idx    = pass ? g_idx2 : g_idx1;

    const int tid  = threadIdx.x;
    const int lane = tid & 31;
    const int warp = tid >> 5;           // 8 warps, warp owns rows warp*8..+8
    const int rowBase = blockIdx.x * ROWS_BLK;

    // ---- load A transposed (once): X[rowBase+r][d] -> As[d][r] ----
    // warp w covers d-range w*32..w*32+31; lane indexes the row -> conflict-free STS.
    {
        #pragma unroll
        for (int rr = 0; rr < 2; rr++) {
            int r = rr * 32 + lane;
            const float* src = &X[(size_t)(rowBase + r) * D_ + warp * 32];
            #pragma unroll
            for (int q = 0; q < 8; q++) {
                float4 v = *(const float4*)(src + q * 4);
                As[warp * 32 + q * 4 + 0][r] = v.x;
                As[warp * 32 + q * 4 + 1][r] = v.y;
                As[warp * 32 + q * 4 + 2][r] = v.z;
                As[warp * 32 + q * 4 + 3][r] = v.w;
            }
        }
        if (tid < ROWS_BLK) x2s[tid] = g_x2[rowBase + tid];
    }

    float rmin[8];
    int   ridx[8];
    #pragma unroll
    for (int i = 0; i < 8; i++) { rmin[i] = 3.4e38f; ridx[i] = 0; }

    for (int ct = 0; ct < K_; ct += 256) {
        unsigned long long acc2[4][8];
        #pragma unroll
        for (int i = 0; i < 4; i++)
            #pragma unroll
            for (int j = 0; j < 8; j++) acc2[i][j] = 0ull;

        for (int d0 = 0; d0 < D_; d0 += 32) {
            __syncthreads();   // prev chunk consumed (also orders A-load on first pass)
            // load B chunk transposed: thread owns col c = tid; conflict-free STS.
            {
                const float* src = &E[(size_t)(ct + tid) * D_ + d0];
                #pragma unroll
                for (int q = 0; q < 8; q++) {
                    float4 u = *(const float4*)(src + q * 4);
                    Bs[q * 4 + 0][tid] = u.x;
                    Bs[q * 4 + 1][tid] = u.y;
                    Bs[q * 4 + 2][tid] = u.z;
                    Bs[q * 4 + 3][tid] = u.w;
                }
            }
            __syncthreads();
            #pragma unroll 4
            for (int d = 0; d < 32; d++) {
                const ulonglong2* ap = (const ulonglong2*)&As[d0 + d][warp * 8];
                ulonglong2 p0 = ap[0], p1 = ap[1];
                unsigned long long a2[4];
                a2[0] = p0.x; a2[1] = p0.y; a2[2] = p1.x; a2[3] = p1.y;
                #pragma unroll
                for (int jh = 0; jh < 2; jh++) {
                    float4 bb = *(const float4*)&Bs[d][lane * 8 + jh * 4];
                    unsigned long long b2[4];
                    b2[0] = pack2(bb.x); b2[1] = pack2(bb.y);
                    b2[2] = pack2(bb.z); b2[3] = pack2(bb.w);
                    #pragma unroll
                    for (int i = 0; i < 4; i++)
                        #pragma unroll
                        for (int j = 0; j < 4; j++)
                            acc2[i][jh * 4 + j] = ffma2(a2[i], b2[j], acc2[i][jh * 4 + j]);
                }
            }
        }
        // ---- fold this 256-col tile into running argmin (exact reference rounding) ----
        float xv[8];
        #pragma unroll
        for (int i = 0; i < 8; i++) xv[i] = x2s[warp * 8 + i];
        #pragma unroll
        for (int j = 0; j < 8; j++) {
            int col = ct + lane * 8 + j;
            float ev = __ldg(&e2[col]);
            #pragma unroll
            for (int i = 0; i < 4; i++) {
                float mlo = __uint_as_float((unsigned)(acc2[i][j] & 0xffffffffull));
                float mhi = __uint_as_float((unsigned)(acc2[i][j] >> 32));
                float sc0 = __fadd_rn(__fadd_rn(xv[2 * i],     __fmul_rn(-2.0f, mlo)), ev);
                float sc1 = __fadd_rn(__fadd_rn(xv[2 * i + 1], __fmul_rn(-2.0f, mhi)), ev);
                if (sc0 < rmin[2 * i])     { rmin[2 * i] = sc0;     ridx[2 * i] = col; }
                if (sc1 < rmin[2 * i + 1]) { rmin[2 * i + 1] = sc1; ridx[2 * i + 1] = col; }
            }
        }
    }

    // ---- cross-lane reduce: each row's 32 lane-partials, lowest index on ties ----
    #pragma unroll
    for (int rr = 0; rr < 8; rr++) {
        unsigned long long b = pack_min(rmin[rr], ridx[rr]);
        #pragma unroll
        for (int o = 16; o > 0; o >>= 1) {
            unsigned long long v = __shfl_xor_sync(0xffffffffu, b, o);
            if (v < b) b = v;
        }
        if (lane == 0) out_idx[rowBase + warp * 8 + rr] = (int)(b & 0xffffffffu);
    }
}

// ---------------- quantize + loss + segment sums (pass A) ----------------
__global__ void stats_kernel(const float* __restrict__ X, const float* __restrict__ E,
                             float* __restrict__ out_quant, float* __restrict__ out_idxf)
{
    int n = blockIdx.x;
    int d = threadIdx.x;
    int idx = g_idx1[n];
    float xv = X[(size_t)n * D_ + d];
    float q  = E[(size_t)idx * D_ + d];
    float quant = __fadd_rn(xv, __fadd_rn(q, -xv));   // fl(x + fl(q - x))
    out_quant[(size_t)n * D_ + d] = quant;
    float diff = __fadd_rn(xv, -quant);
    float v = __fmul_rn(diff, diff);
    __shared__ float sh[8];
    #pragma unroll
    for (int o = 16; o > 0; o >>= 1) v += __shfl_down_sync(0xffffffffu, v, o);
    if ((d & 31) == 0) sh[d >> 5] = v;
    __syncthreads();
    atomicAdd(&g_dw[(size_t)idx * D_ + d], xv);
    if (d == 0) {
        float s = 0.0f;
        #pragma unroll
        for (int w = 0; w < 8; w++) s += sh[w];
        atomicAdd(&g_loss_part[n & 255], (double)s);
        out_idxf[n] = (float)idx;
        atomicAdd(&g_counts[idx], 1.0f);
    }
}

// ---------------- new_cs, new_usage, n-sum, usage count ----------------
__global__ void cs_kernel(const float* __restrict__ ema_cs, const float* __restrict__ usage,
                          float* __restrict__ out_cs, float* __restrict__ out_usage)
{
    int k = blockIdx.x * 256 + threadIdx.x;   // grid = 16
    float c = g_counts[k];
    float ncs = __fadd_rn(__fmul_rn(ema_cs[k], 0.99f), __fmul_rn(0.01f, c));
    out_cs[k] = ncs;
    float nu = __fadd_rn(__fmul_rn(usage[k], 0.99f), __fmul_rn(0.01f, c));
    out_usage[k] = nu;

    float v = ncs;
    __shared__ float sh[8];
    #pragma unroll
    for (int o = 16; o > 0; o >>= 1) v += __shfl_down_sync(0xffffffffu, v, o);
    if ((threadIdx.x & 31) == 0) sh[threadIdx.x >> 5] = v;

    unsigned bal = __ballot_sync(0xffffffffu, nu > 0.0f);
    if ((threadIdx.x & 31) == 0) atomicAdd(&g_usage_cnt, __popc(bal));

    __syncthreads();
    if (threadIdx.x == 0) {
        float s = 0.0f;
        #pragma unroll
        for (int w = 0; w < 8; w++) s += sh[w];
        atomicAdd(&g_nsum, s);
    }
}

// ---------------- new_ema_w, new_embedding (to out + aligned scratch) ----------------
__global__ void emb_kernel(const float* __restrict__ ema_w, const float* __restrict__ out_cs,
                           float* __restrict__ out_ema_w, float* __restrict__ out_emb)
{
    int k = blockIdx.x;
    int d = threadIdx.x;
    float ncs = out_cs[k];
    float n = g_nsum;
    float csz = __fmul_rn(__fdiv_rn(__fadd_rn(ncs, 1e-5f),
                                    __fadd_rn(n, (float)K_ * 1e-5f)), n);
    float w = __fadd_rn(__fmul_rn(ema_w[(size_t)k * D_ + d], 0.99f),
                        __fmul_rn(0.01f, g_dw[(size_t)k * D_ + d]));
    out_ema_w[(size_t)k * D_ + d] = w;
    float e = __fdiv_rn(w, csz);
    out_emb[(size_t)k * D_ + d] = e;
    g_embB[(size_t)k * D_ + d] = e;            // aligned copy for pass-B argmin
}

// ---------------- scalars: loss, usage_rate ----------------
__global__ void scalar_kernel(float* __restrict__ out_loss, float* __restrict__ out_urate) {
    double s = 0.0;
    for (int i = 0; i < 256; i++) s += g_loss_part[i];
    *out_loss = 0.25f * (float)(s / ((double)N_ * (double)D_));
    *out_urate = (float)g_usage_cnt / (float)K_;
}

// ---------------- used mask from pass B ----------------
__global__ void used_kernel() {
    int i = blockIdx.x * 256 + threadIdx.x;   // grid = 128
    g_used[g_idx2[i]] = 1;
}

// ---------------- dead-code reset + steps output ----------------
__global__ void finalize_kernel(const float* __restrict__ X, const int* __restrict__ steps_in,
                                const int* __restrict__ rnd, float* __restrict__ out_emb,
                                float* __restrict__ out_steps)
{
    int k = blockIdx.x;
    int d = threadIdx.x;
    int used = g_used[k];
    float stepv = used ? 0.0f : ((float)steps_in[k] + 1.0f);
    bool dead = stepv > 100.0f;
    if (dead) {
        int r = rnd[k];
        out_emb[(size_t)k * D_ + d] = X[(size_t)r * D_ + d];
    }
    if (d == 0) out_steps[k] = dead ? 0.0f : stepv;
}

// ---------------- launch ----------------
extern "C" void kernel_launch(void* const* d_in, const int* in_sizes, int n_in,
                              void* d_out, int out_size)
{
    const float* x       = (const float*)d_in[0];
    const float* emb     = (const float*)d_in[1];
    const float* ema_cs  = (const float*)d_in[2];
    const float* ema_w   = (const float*)d_in[3];
    const float* usage   = (const float*)d_in[4];
    const int*   steps_i = (const int*)d_in[5];
    const int*   rnd     = (const int*)d_in[6];

    float* out     = (float*)d_out;
    float* o_quant = out;                         // N*D
    float* o_idx   = o_quant + (size_t)N_ * D_;   // N
    float* o_loss  = o_idx + N_;                  // 1
    float* o_emb   = o_loss + 1;                  // K*D (only 4B-aligned; scalar access only)
    float* o_cs    = o_emb + (size_t)K_ * D_;     // K
    float* o_emaw  = o_cs + K_;                   // K*D
    float* o_usage = o_emaw + (size_t)K_ * D_;    // K
    float* o_steps = o_usage + K_;                // K
    float* o_urate = o_steps + K_;                // 1

    float* embB_dev = nullptr;
    cudaGetSymbolAddress((void**)&embB_dev, g_embB);
    float* x2_dev = nullptr;
    cudaGetSymbolAddress((void**)&x2_dev, g_x2);
    float* e2a_dev = nullptr;
    cudaGetSymbolAddress((void**)&e2a_dev, g_e2a);
    float* e2b_dev = nullptr;
    cudaGetSymbolAddress((void**)&e2b_dev, g_e2b);

    static int smem_configured = 0;
    if (!smem_configured) {
        cudaFuncSetAttribute(argmin_kernel,
                             cudaFuncAttributeMaxDynamicSharedMemorySize, SMEM_ARG);
        smem_configured = 1;
    }

    init_kernel<<<(K_ * D_) / 256, 256>>>();
    rowsq_kernel<<<N_ / 8, 256>>>(x, x2_dev, N_);          // x2 (bit-critical)
    rowsq_kernel<<<K_ / 8, 256>>>(emb, e2a_dev, K_);       // e2 pass A
    argmin_kernel<<<N_ / ROWS_BLK, 256, SMEM_ARG>>>(x, emb, 0);
    stats_kernel<<<N_, 256>>>(x, emb, o_quant, o_idx);
    cs_kernel<<<K_ / 256, 256>>>(ema_cs, usage, o_cs, o_usage);
    emb_kernel<<<K_, 256>>>(ema_w, o_cs, o_emaw, o_emb);
    scalar_kernel<<<1, 1>>>(o_loss, o_urate);
    rowsq_kernel<<<K_ / 8, 256>>>(embB_dev, e2b_dev, K_);  // e2 pass B
    argmin_kernel<<<N_ / ROWS_BLK, 256, SMEM_ARG>>>(x, embB_dev, 1);
    used_kernel<<<N_ / 256, 256>>>();
    finalize_kernel<<<K_, 256>>>(x, steps_i, rnd, o_emb, o_steps);
}